// round 11
// baseline (speedup 1.0000x reference)
#include <cuda_runtime.h>
#include <cuda_fp16.h>
#include <cstdint>
#include <math.h>

// Problem constants
#define BB 8
#define TT 1024
#define DD 1024
#define NHEAD 16
#define HDIM 64
#define FF 4096
#define MM (BB * TT)   // 8192
#define QKVN 3072

// ---------------------------------------------------------------------------
// Scratch (device globals)
// ---------------------------------------------------------------------------
__device__ __half g_xn [MM * DD];
__device__ __half g_qkv[MM * QKVN];
__device__ __half g_ao [MM * DD];
__device__ float  g_ar [MM * DD];
__device__ __half g_hn [MM * DD];
__device__ __half g_h1 [MM * FF];
__device__ __half g_wqkvt[QKVN * DD];   // [3072][1024] K-major (q|k|v)
__device__ float  g_bqkv [QKVN];
__device__ __half g_wot[DD * DD];
__device__ __half g_w1t[FF * DD];
__device__ __half g_w2t[DD * FF];

// ---------------------------------------------------------------------------
// Helpers
// ---------------------------------------------------------------------------
__device__ __forceinline__ uint32_t s2u(const void* p) {
    uint32_t a;
    asm("{ .reg .u64 t; cvta.to.shared.u64 t, %1; cvt.u32.u64 %0, t; }"
        : "=r"(a) : "l"(p));
    return a;
}

__device__ __forceinline__ void cp_async16(uint32_t saddr, const void* gaddr) {
    asm volatile("cp.async.cg.shared.global [%0], [%1], 16;"
                 :: "r"(saddr), "l"(gaddr));
}
__device__ __forceinline__ void cp_async4(uint32_t saddr, const void* gaddr) {
    asm volatile("cp.async.ca.shared.global [%0], [%1], 4;"
                 :: "r"(saddr), "l"(gaddr));
}
__device__ __forceinline__ void cp_commit() {
    asm volatile("cp.async.commit_group;");
}
template <int N>
__device__ __forceinline__ void cp_wait() {
    asm volatile("cp.async.wait_group %0;" :: "n"(N));
}

__device__ __forceinline__ void ldsm4(uint32_t& r0, uint32_t& r1,
                                      uint32_t& r2, uint32_t& r3, uint32_t addr) {
    asm volatile("ldmatrix.sync.aligned.m8n8.x4.shared.b16 {%0,%1,%2,%3}, [%4];"
                 : "=r"(r0), "=r"(r1), "=r"(r2), "=r"(r3) : "r"(addr));
}
__device__ __forceinline__ void ldsm4t(uint32_t& r0, uint32_t& r1,
                                       uint32_t& r2, uint32_t& r3, uint32_t addr) {
    asm volatile("ldmatrix.sync.aligned.m8n8.x4.trans.shared.b16 {%0,%1,%2,%3}, [%4];"
                 : "=r"(r0), "=r"(r1), "=r"(r2), "=r"(r3) : "r"(addr));
}

// fp16 MMA m16n8k16, fp32 accumulate
__device__ __forceinline__ void mma_f16(float* c, const uint32_t* a,
                                        uint32_t b0, uint32_t b1) {
    asm volatile(
        "mma.sync.aligned.m16n8k16.row.col.f32.f16.f16.f32 "
        "{%0,%1,%2,%3}, {%4,%5,%6,%7}, {%8,%9}, {%0,%1,%2,%3};"
        : "+f"(c[0]), "+f"(c[1]), "+f"(c[2]), "+f"(c[3])
        : "r"(a[0]), "r"(a[1]), "r"(a[2]), "r"(a[3]), "r"(b0), "r"(b1));
}

__device__ __forceinline__ uint32_t pkh2(float a, float b) {
    const __half2 h = __floats2half2_rn(a, b);
    return *(const uint32_t*)&h;
}

// ---------------------------------------------------------------------------
// Fused prep kernel
// ---------------------------------------------------------------------------
__device__ __forceinline__ void transpose_tile(
    const float* __restrict__ in, __half* __restrict__ out,
    int bx, int by, int C, int R, float (*t)[33], int tid)
{
    const int txx = tid & 31, tyy = tid >> 5;
    #pragma unroll
    for (int j = 0; j < 32; j += 8)
        t[tyy + j][txx] = in[(size_t)(by + tyy + j) * C + bx + txx];
    __syncthreads();
    #pragma unroll
    for (int j = 0; j < 32; j += 8)
        out[(size_t)(bx + tyy + j) * R + by + txx] = __float2half_rn(t[txx][tyy + j]);
}

#define PREP_BLOCKS 12300

__global__ __launch_bounds__(256) void prep_kernel(
    const float* __restrict__ wq, const float* __restrict__ wk,
    const float* __restrict__ wv, const float* __restrict__ w1,
    const float* __restrict__ w2, const float* __restrict__ wo,
    const float* __restrict__ bq, const float* __restrict__ bk,
    const float* __restrict__ bv,
    __half* __restrict__ wqkvt, __half* __restrict__ w1t,
    __half* __restrict__ w2t, __half* __restrict__ wot,
    float* __restrict__ bqkv)
{
    __shared__ float t[32][33];
    const int id = blockIdx.x;
    const int tid = threadIdx.x;

    if (id < 3072) {
        const int w = id >> 10, tt = id & 1023;
        const float* in = (w == 0) ? wq : (w == 1) ? wk : wv;
        __half* outp = wqkvt + (size_t)w * 1024 * DD;
        transpose_tile(in, outp, (tt & 31) << 5, (tt >> 5) << 5, DD, DD, t, tid);
    } else if (id < 7168) {
        const int tt = id - 3072;
        transpose_tile(w1, w1t, (tt & 127) << 5, (tt >> 7) << 5, FF, DD, t, tid);
    } else if (id < 11264) {
        const int tt = id - 7168;
        transpose_tile(w2, w2t, (tt & 31) << 5, (tt >> 5) << 5, DD, FF, t, tid);
    } else if (id < 12288) {
        const int i = (id - 11264) * 1024 + tid * 4;
        const float4 v = *(const float4*)(wo + i);
        __half2* o2 = (__half2*)(wot + i);
        o2[0] = __floats2half2_rn(v.x, v.y);
        o2[1] = __floats2half2_rn(v.z, v.w);
    } else {
        const int i = (id - 12288) * 256 + tid;
        if (i < QKVN)
            bqkv[i] = (i < 1024) ? bq[i] : (i < 2048) ? bk[i - 1024] : bv[i - 2048];
    }
}

// ---------------------------------------------------------------------------
// RMSNorm / LayerNorm: warp-per-row
// ---------------------------------------------------------------------------
__global__ __launch_bounds__(256) void rmsnorm_kernel(
    const float* __restrict__ x, const float* __restrict__ scale,
    __half* __restrict__ out)
{
    const int lane = threadIdx.x & 31;
    const int row = blockIdx.x * 8 + (threadIdx.x >> 5);
    const float4* xp = (const float4*)(x + (size_t)row * DD);
    const float4* sp = (const float4*)scale;
    float4 v[8];
    float ss = 0.f;
    #pragma unroll
    for (int u = 0; u < 8; u++) {
        v[u] = xp[lane + 32 * u];
        ss += v[u].x * v[u].x + v[u].y * v[u].y + v[u].z * v[u].z + v[u].w * v[u].w;
    }
    #pragma unroll
    for (int m = 16; m; m >>= 1) ss += __shfl_xor_sync(0xffffffffu, ss, m);
    const float r = rsqrtf(ss * (1.0f / DD) + 1e-6f);
    __half2* o2 = (__half2*)(out + (size_t)row * DD);
    #pragma unroll
    for (int u = 0; u < 8; u++) {
        const float4 s4 = sp[lane + 32 * u];
        o2[(lane + 32 * u) * 2 + 0] = __floats2half2_rn(v[u].x * r * s4.x, v[u].y * r * s4.y);
        o2[(lane + 32 * u) * 2 + 1] = __floats2half2_rn(v[u].z * r * s4.z, v[u].w * r * s4.w);
    }
}

__global__ __launch_bounds__(256) void layernorm_kernel(
    const float* __restrict__ x, const float* __restrict__ gamma,
    const float* __restrict__ beta, __half* __restrict__ out)
{
    const int lane = threadIdx.x & 31;
    const int row = blockIdx.x * 8 + (threadIdx.x >> 5);
    const float4* xp = (const float4*)(x + (size_t)row * DD);
    float4 v[8];
    float s = 0.f, ss = 0.f;
    #pragma unroll
    for (int u = 0; u < 8; u++) {
        v[u] = xp[lane + 32 * u];
        s  += v[u].x + v[u].y + v[u].z + v[u].w;
        ss += v[u].x * v[u].x + v[u].y * v[u].y + v[u].z * v[u].z + v[u].w * v[u].w;
    }
    #pragma unroll
    for (int m = 16; m; m >>= 1) {
        s  += __shfl_xor_sync(0xffffffffu, s,  m);
        ss += __shfl_xor_sync(0xffffffffu, ss, m);
    }
    const float mean = s * (1.0f / DD);
    const float var  = ss * (1.0f / DD) - mean * mean;
    const float r = rsqrtf(var + 1e-5f);
    __half2* o2 = (__half2*)(out + (size_t)row * DD);
    const float4* gp = (const float4*)gamma;
    const float4* bp = (const float4*)beta;
    #pragma unroll
    for (int u = 0; u < 8; u++) {
        const float4 g4 = gp[lane + 32 * u];
        const float4 b4 = bp[lane + 32 * u];
        o2[(lane + 32 * u) * 2 + 0] = __floats2half2_rn(
            (v[u].x - mean) * r * g4.x + b4.x, (v[u].y - mean) * r * g4.y + b4.y);
        o2[(lane + 32 * u) * 2 + 1] = __floats2half2_rn(
            (v[u].z - mean) * r * g4.z + b4.z, (v[u].w - mean) * r * g4.w + b4.w);
    }
}

// ---------------------------------------------------------------------------
// Persistent fp16 mma.sync GEMM: fixed grid, each CTA loops over tiles.
// ---------------------------------------------------------------------------
__device__ __forceinline__ float softplus_f(float x) {
    return (x > 15.f) ? x : log1pf(__expf(x));
}

#define GSTAGE 32768
#define GEMM_SMEM_BYTES (3 * GSTAGE)
#define GEMM_GRID 296

template <int EPI, bool OUTH>
__global__ __launch_bounds__(256, 2) void mma_gemm_kernel(
    const __half* __restrict__ A, const __half* __restrict__ Bw,
    const float* __restrict__ bias, const float* __restrict__ extra,
    void* __restrict__ Cv, int M, int N, int K)
{
    extern __shared__ char gsm[];
    const uint32_t smbase = s2u(gsm);
    const int tid = threadIdx.x;
    const int lane = tid & 31;
    const int wid = tid >> 5;
    const int wm = (wid & 3) << 5;
    const int wn = (wid >> 2) << 6;

    // tile-independent loader precompute
    const int lm = tid >> 3;           // row within tile (0..127) per u-chunk base
    const int lkc = tid & 7;
    uint32_t a_soff[4], b_soff[4];
    int am[4];
    #pragma unroll
    for (int u = 0; u < 4; u++) {
        const int qch = tid + u * 256;
        const int m = qch >> 3, kc = qch & 7;
        const uint32_t sw = (uint32_t)(kc ^ (m & 7));
        a_soff[u] = (uint32_t)(m * 128) + (sw << 4);
        b_soff[u] = a_soff[u] + 16384u;
        am[u] = m;
    }
    (void)lm; (void)lkc;

    const int arow = wm + (lane & 15);
    const uint32_t acadd = (uint32_t)(lane >> 4);
    const uint32_t aswz = (uint32_t)(arow & 7);
    const uint32_t aoff = (uint32_t)(arow * 128);
    const int brow = wn + ((lane >> 4) << 3) + (lane & 7);
    const uint32_t bcc = (uint32_t)((lane >> 3) & 1);
    const uint32_t bswz = (uint32_t)(brow & 7);
    const uint32_t boff = (uint32_t)(brow * 128) + 16384u;
    const int g = lane >> 2, tg = lane & 3;
    const int nk = K >> 6;
    const int nbx = N >> 7;
    const int ntiles = (M >> 7) * nbx;

    for (int t = blockIdx.x; t < ntiles; t += GEMM_GRID) {
        const int m0 = (t / nbx) << 7;
        const int n0 = (t % nbx) << 7;

        const __half* a_g[4]; const __half* b_g[4];
        #pragma unroll
        for (int u = 0; u < 4; u++) {
            const int qch = tid + u * 256;
            const int kc = qch & 7;
            a_g[u] = A  + (size_t)(m0 + am[u]) * K + kc * 8;
            b_g[u] = Bw + (size_t)(n0 + am[u]) * K + kc * 8;
        }

        float acc[2][8][4];
        #pragma unroll
        for (int i = 0; i < 2; i++)
            #pragma unroll
            for (int j = 0; j < 8; j++)
                #pragma unroll
                for (int q = 0; q < 4; q++) acc[i][j][q] = 0.f;

        #pragma unroll
        for (int s = 0; s < 2; s++) {
            const uint32_t sb = smbase + (uint32_t)s * GSTAGE;
            #pragma unroll
            for (int u = 0; u < 4; u++) {
                cp_async16(sb + a_soff[u], a_g[u] + s * 64);
                cp_async16(sb + b_soff[u], b_g[u] + s * 64);
            }
            cp_commit();
        }

        int sidx = 0;
        for (int kc = 0; kc < nk; kc++) {
            if (kc == nk - 1) cp_wait<0>(); else cp_wait<1>();
            __syncthreads();
            if (kc + 2 < nk) {
                const int s2 = (sidx + 2 >= 3) ? sidx - 1 : sidx + 2;
                const uint32_t sb = smbase + (uint32_t)s2 * GSTAGE;
                #pragma unroll
                for (int u = 0; u < 4; u++) {
                    cp_async16(sb + a_soff[u], a_g[u] + (kc + 2) * 64);
                    cp_async16(sb + b_soff[u], b_g[u] + (kc + 2) * 64);
                }
                cp_commit();
            }
            const uint32_t sb = smbase + (uint32_t)sidx * GSTAGE;
            #pragma unroll
            for (int ks = 0; ks < 4; ks++) {
                const uint32_t kc0 = (uint32_t)(2 * ks);
                uint32_t af[2][4];
                #pragma unroll
                for (int i = 0; i < 2; i++) {
                    const uint32_t addr = sb + aoff + (uint32_t)(i * 2048) +
                                          (((kc0 + acadd) ^ aswz) << 4);
                    ldsm4(af[i][0], af[i][1], af[i][2], af[i][3], addr);
                }
                #pragma unroll
                for (int jp = 0; jp < 4; jp++) {
                    uint32_t b0, b1, b2, b3;
                    const uint32_t addr = sb + boff + (uint32_t)(jp * 2048) +
                                          (((kc0 + bcc) ^ bswz) << 4);
                    ldsm4(b0, b1, b2, b3, addr);
                    #pragma unroll
                    for (int i = 0; i < 2; i++) {
                        mma_f16(acc[i][2 * jp + 0], af[i], b0, b1);
                        mma_f16(acc[i][2 * jp + 1], af[i], b2, b3);
                    }
                }
            }
            sidx = (sidx == 2) ? 0 : sidx + 1;
        }

        // epilogue
        #pragma unroll
        for (int i = 0; i < 2; i++) {
            #pragma unroll
            for (int j = 0; j < 8; j++) {
                const int col = n0 + wn + j * 8 + tg * 2;
                const float2 b2 = *(const float2*)(bias + col);
                float sx = 1.f, sy = 1.f;
                if (EPI == 1) {
                    if (col < 1024) {
                        // LOG2E^2 / sqrt(64): extra LOG2E folds softmax into exp2
                        const float c = 0.26017101f;
                        sx = c * softplus_f(extra[col & 63]);
                        sy = c * softplus_f(extra[(col + 1) & 63]);
                    }
                }
                #pragma unroll
                for (int h = 0; h < 2; h++) {
                    const int row = m0 + wm + i * 16 + g + h * 8;
                    float vx = acc[i][j][2 * h + 0] + b2.x;
                    float vy = acc[i][j][2 * h + 1] + b2.y;
                    if (EPI == 1) { vx *= sx; vy *= sy; }
                    if (EPI == 2) {
                        const float2 r2 = *(const float2*)(extra + (size_t)row * N + col);
                        vx += r2.x; vy += r2.y;
                    }
                    if (EPI == 3) { vx = fmaxf(vx, 0.f); vy = fmaxf(vy, 0.f); }
                    if (OUTH) {
                        *(__half2*)((__half*)Cv + (size_t)row * N + col) =
                            __floats2half2_rn(vx, vy);
                    } else {
                        float2 o2; o2.x = vx; o2.y = vy;
                        *(float2*)((float*)Cv + (size_t)row * N + col) = o2;
                    }
                }
            }
        }
        __syncthreads();   // protect smem before next tile's prologue
    }
}

// ---------------------------------------------------------------------------
// Flash attention v5 (unchanged from R9 — proven)
// ---------------------------------------------------------------------------
#define FL_PQ_I 12288   // float idx: padq[128]
#define FL_PS_I 12416   // pads[2][64]
#define FLASH_SMEM_BYTES 50176

__global__ __launch_bounds__(256) void flash_kernel(
    const __half* __restrict__ qkv, const float* __restrict__ pad,
    __half* __restrict__ out)
{
    extern __shared__ float sf[];
    const uint32_t sbase = s2u(sf);
    const int tid = threadIdx.x;
    const int lane = tid & 31;
    const int wid = tid >> 5;
    const int wm = wid << 4;
    const int g = lane >> 2, tg = lane & 3;
    const int t0 = (7 - blockIdx.x) << 7;         // longest first
    const int b = blockIdx.y >> 4, n = blockIdx.y & 15;

    const int arow = wm + (lane & 15);
    const uint32_t acadd = (uint32_t)(lane >> 4);
    const uint32_t aswz = (uint32_t)(arow & 7);
    const uint32_t qbase = sbase + (uint32_t)(arow * 128);
    const int brw = ((lane >> 4) << 3) + (lane & 7);
    const uint32_t bcc = (uint32_t)((lane >> 3) & 1);
    const int vkr = ((lane >> 3) & 1) * 8 + (lane & 7);
    const int vcc = lane >> 4;

    // ---- load Q tile + padq
    {
        const int r = tid >> 1;
        const int c0 = (tid & 1) << 2;
        const __half* qp = qkv + (size_t)(b * TT + t0 + r) * QKVN + n * 64;
        #pragma unroll
        for (int u = 0; u < 4; u++) {
            const int c = c0 + u;
            cp_async16(sbase + (uint32_t)(r * 128 + ((c ^ (r & 7)) << 4)),
                       qp + c * 8);
        }
        if (tid < 128)
            cp_async4(sbase + (uint32_t)((FL_PQ_I + tid) * 4),
                      pad + b * TT + t0 + tid);
    }
    // ---- prefetch first K/V tile into buf 0
    {
        const int lr = tid >> 2;
        const int lc0 = (tid & 3) << 1;
        const __half* kp = qkv + (size_t)(b * TT + lr) * QKVN + 1024 + n * 64;
        const __half* vp = kp + 1024;
        #pragma unroll
        for (int u = 0; u < 2; u++) {
            const int c = lc0 + u;
            const uint32_t so = (uint32_t)(lr * 128 + ((c ^ (lr & 7)) << 4));
            cp_async16(sbase + 16384u + so, kp + c * 8);
            cp_async16(sbase + 24576u + so, vp + c * 8);
        }
        if (tid < 64)
            cp_async4(sbase + (uint32_t)((FL_PS_I + tid) * 4), pad + b * TT + tid);
    }
    cp_commit();

    float o[8][4];
    #pragma unroll
    for (int j = 0; j < 8; j++)
        #pragma unroll
        for (int c = 0; c < 4; c++) o[j][c] = 0.f;
    float m0 = -1e30f, m1 = -1e30f, l0 = 0.f, l1 = 0.f;
    const int r0l = wm + g, r1l = r0l + 8;

    const int nIter = (t0 >> 6) + 2;
    for (int it = 0; it < nIter; it++) {
        const int s0 = it << 6;
        const int buf = it & 1;
        const uint32_t kbuf = sbase + 16384u + (uint32_t)buf * 16384u;
        const uint32_t vbuf = kbuf + 8192u;

        cp_wait<0>();
        __syncthreads();

        if (it + 1 < nIter) {
            const int lr = tid >> 2;
            const int lc0 = (tid & 3) << 1;
            const __half* kp = qkv + (size_t)(b * TT + s0 + 64 + lr) * QKVN + 1024 + n * 64;
            const __half* vp = kp + 1024;
            const uint32_t ob = sbase + 16384u + (uint32_t)(buf ^ 1) * 16384u;
            #pragma unroll
            for (int u = 0; u < 2; u++) {
                const int c = lc0 + u;
                const uint32_t so = (uint32_t)(lr * 128 + ((c ^ (lr & 7)) << 4));
                cp_async16(ob + so, kp + c * 8);
                cp_async16(ob + 8192u + so, vp + c * 8);
            }
            if (tid < 64)
                cp_async4(sbase + (uint32_t)((FL_PS_I + (buf ^ 1) * 64 + tid) * 4),
                          pad + b * TT + s0 + 64 + tid);
            cp_commit();
        }

        // ---- S = Q K^T
        float sacc[8][4];
        #pragma unroll
        for (int j = 0; j < 8; j++)
            #pragma unroll
            for (int c = 0; c < 4; c++) sacc[j][c] = 0.f;
        #pragma unroll
        for (int ks = 0; ks < 4; ks++) {
            const uint32_t kc0 = (uint32_t)(2 * ks);
            uint32_t af[4];
            ldsm4(af[0], af[1], af[2], af[3],
                  qbase + (((kc0 + acadd) ^ aswz) << 4));
            #pragma unroll
            for (int jp = 0; jp < 4; jp++) {
                const int brow = jp * 16 + brw;
                uint32_t b0, b1, b2, b3;
                ldsm4(b0, b1, b2, b3,
                      kbuf + (uint32_t)(brow * 128) +
                      (((kc0 + bcc) ^ (uint32_t)(brow & 7)) << 4));
                mma_f16(sacc[2 * jp + 0], af, b0, b1);
                mma_f16(sacc[2 * jp + 1], af, b2, b3);
            }
        }

        // ---- additive masking (warp-uniform causal branch)
        const float pq0 = sf[FL_PQ_I + r0l], pq1 = sf[FL_PQ_I + r1l];
        const float pqa0 = (pq0 != 0.f) ? 0.f : -1e9f;
        const float pqa1 = (pq1 != 0.f) ? 0.f : -1e9f;
        const int rg0 = t0 + r0l, rg1 = t0 + r1l;
        const int psb = FL_PS_I + buf * 64;
        if (s0 + 64 <= t0 + wm) {
            #pragma unroll
            for (int j = 0; j < 8; j++) {
                const int cl = j * 8 + 2 * tg;
                const float psa0 = (sf[psb + cl]     != 0.f) ? 0.f : -1e9f;
                const float psa1 = (sf[psb + cl + 1] != 0.f) ? 0.f : -1e9f;
                sacc[j][0] += pqa0 + psa0;
                sacc[j][1] += pqa0 + psa1;
                sacc[j][2] += pqa1 + psa0;
                sacc[j][3] += pqa1 + psa1;
            }
        } else {
            #pragma unroll
            for (int j = 0; j < 8; j++) {
                const int cl = j * 8 + 2 * tg;
                const int cg = s0 + cl;
                const float psa0 = (sf[psb + cl]     != 0.f) ? 0.f : -1e9f;
                const float psa1 = (sf[psb + cl + 1] != 0.f) ? 0.f : -1e9f;
                sacc[j][0] += pqa0 + psa0 + ((cg     <= rg0) ? 0.f : -1e9f);
                sacc[j][1] += pqa0 + psa1 + ((cg + 1 <= rg0) ? 0.f : -1e9f);
                sacc[j][2] += pqa1 + psa0 + ((cg     <= rg1) ? 0.f : -1e9f);
                sacc[j][3] += pqa1 + psa1 + ((cg + 1 <= rg1) ? 0.f : -1e9f);
            }
        }

        // ---- warp-local online softmax in log2 domain
        float rm0 = -1e30f, rm1 = -1e30f;
        #pragma unroll
        for (int j = 0; j < 8; j++) {
            rm0 = fmaxf(rm0, fmaxf(sacc[j][0], sacc[j][1]));
            rm1 = fmaxf(rm1, fmaxf(sacc[j][2], sacc[j][3]));
        }
        rm0 = fmaxf(rm0, __shfl_xor_sync(0xffffffffu, rm0, 1));
        rm0 = fmaxf(rm0, __shfl_xor_sync(0xffffffffu, rm0, 2));
        rm1 = fmaxf(rm1, __shfl_xor_sync(0xffffffffu, rm1, 1));
        rm1 = fmaxf(rm1, __shfl_xor_sync(0xffffffffu, rm1, 2));
        const float mn0 = fmaxf(m0, rm0), mn1 = fmaxf(m1, rm1);
        const float alpha0 = exp2f(m0 - mn0), alpha1 = exp2f(m1 - mn1);
        m0 = mn0; m1 = mn1;
        float rs0 = 0.f, rs1 = 0.f;
        #pragma unroll
        for (int j = 0; j < 8; j++) {
            sacc[j][0] = exp2f(sacc[j][0] - mn0);
            sacc[j][1] = exp2f(sacc[j][1] - mn0);
            sacc[j][2] = exp2f(sacc[j][2] - mn1);
            sacc[j][3] = exp2f(sacc[j][3] - mn1);
            rs0 += sacc[j][0] + sacc[j][1];
            rs1 += sacc[j][2] + sacc[j][3];
        }
        rs0 += __shfl_xor_sync(0xffffffffu, rs0, 1);
        rs0 += __shfl_xor_sync(0xffffffffu, rs0, 2);
        rs1 += __shfl_xor_sync(0xffffffffu, rs1, 1);
        rs1 += __shfl_xor_sync(0xffffffffu, rs1, 2);
        l0 = l0 * alpha0 + rs0;
        l1 = l1 * alpha1 + rs1;
        #pragma unroll
        for (int j = 0; j < 8; j++) {
            o[j][0] *= alpha0; o[j][1] *= alpha0;
            o[j][2] *= alpha1; o[j][3] *= alpha1;
        }

        // ---- pack P into 4 k16 A-fragments
        uint32_t pa[4][4];
        #pragma unroll
        for (int ks = 0; ks < 4; ks++) {
            pa[ks][0] = pkh2(sacc[2 * ks][0],     sacc[2 * ks][1]);
            pa[ks][1] = pkh2(sacc[2 * ks][2],     sacc[2 * ks][3]);
            pa[ks][2] = pkh2(sacc[2 * ks + 1][0], sacc[2 * ks + 1][1]);
            pa[ks][3] = pkh2(sacc[2 * ks + 1][2], sacc[2 * ks + 1][3]);
        }

        // ---- O += P V
        #pragma unroll
        for (int ks = 0; ks < 4; ks++) {
            const int kr = ks * 16 + vkr;
            #pragma unroll
            for (int jp = 0; jp < 4; jp++) {
                const int c = jp * 2 + vcc;
                uint32_t b0, b1, b2, b3;
                ldsm4t(b0, b1, b2, b3,
                       vbuf + (uint32_t)(kr * 128) +
                       (((uint32_t)c ^ (uint32_t)(kr & 7)) << 4));
                mma_f16(o[2 * jp + 0], pa[ks], b0, b1);
                mma_f16(o[2 * jp + 1], pa[ks], b2, b3);
            }
        }
    }

    // ---- finalize
    const float inv0 = 1.f / l0;
    const float inv1 = 1.f / l1;
    const size_t row0 = (size_t)(b * TT + t0 + r0l);
    const size_t row1 = (size_t)(b * TT + t0 + r1l);
    #pragma unroll
    for (int j = 0; j < 8; j++) {
        const int col = n * 64 + j * 8 + 2 * tg;
        *(__half2*)(out + row0 * DD + col) =
            __floats2half2_rn(o[j][0] * inv0, o[j][1] * inv0);
        *(__half2*)(out + row1 * DD + col) =
            __floats2half2_rn(o[j][2] * inv1, o[j][3] * inv1);
    }
}

// ---------------------------------------------------------------------------
// Host launch
// ---------------------------------------------------------------------------
extern "C" void kernel_launch(void* const* d_in, const int* in_sizes, int n_in,
                              void* d_out, int out_size)
{
    (void)in_sizes; (void)n_in; (void)out_size;
    const float* x         = (const float*)d_in[0];
    const float* padding   = (const float*)d_in[1];
    const float* rms_scale = (const float*)d_in[2];
    const float* pds       = (const float*)d_in[3];
    const float* wq        = (const float*)d_in[4];
    const float* bq        = (const float*)d_in[5];
    const float* wk        = (const float*)d_in[6];
    const float* bk        = (const float*)d_in[7];
    const float* wv        = (const float*)d_in[8];
    const float* bv        = (const float*)d_in[9];
    const float* wo        = (const float*)d_in[10];
    const float* bo        = (const float*)d_in[11];
    const float* ln_gamma  = (const float*)d_in[12];
    const float* ln_beta   = (const float*)d_in[13];
    const float* w1        = (const float*)d_in[14];
    const float* b1        = (const float*)d_in[15];
    const float* w2        = (const float*)d_in[16];
    const float* b2        = (const float*)d_in[17];
    float* out = (float*)d_out;

    __half *xn, *qkv, *ao, *hn, *h1, *wqkvt, *wot, *w1t, *w2t;
    float *ar, *bqkv;
    cudaGetSymbolAddress((void**)&xn,  g_xn);
    cudaGetSymbolAddress((void**)&qkv, g_qkv);
    cudaGetSymbolAddress((void**)&ao,  g_ao);
    cudaGetSymbolAddress((void**)&ar,  g_ar);
    cudaGetSymbolAddress((void**)&hn,  g_hn);
    cudaGetSymbolAddress((void**)&h1,  g_h1);
    cudaGetSymbolAddress((void**)&wqkvt, g_wqkvt);
    cudaGetSymbolAddress((void**)&bqkv,  g_bqkv);
    cudaGetSymbolAddress((void**)&wot, g_wot);
    cudaGetSymbolAddress((void**)&w1t, g_w1t);
    cudaGetSymbolAddress((void**)&w2t, g_w2t);

    static int attr_done = 0;
    if (!attr_done) {
        cudaFuncSetAttribute(flash_kernel,
            cudaFuncAttributeMaxDynamicSharedMemorySize, FLASH_SMEM_BYTES);
        cudaFuncSetAttribute(mma_gemm_kernel<1, true>,
            cudaFuncAttributeMaxDynamicSharedMemorySize, GEMM_SMEM_BYTES);
        cudaFuncSetAttribute(mma_gemm_kernel<2, false>,
            cudaFuncAttributeMaxDynamicSharedMemorySize, GEMM_SMEM_BYTES);
        cudaFuncSetAttribute(mma_gemm_kernel<3, true>,
            cudaFuncAttributeMaxDynamicSharedMemorySize, GEMM_SMEM_BYTES);
        attr_done = 1;
    }

    // 0. Fused weight prep
    prep_kernel<<<PREP_BLOCKS, 256>>>(wq, wk, wv, w1, w2, wo, bq, bk, bv,
                                      wqkvt, w1t, w2t, wot, bqkv);

    // 1. RMSNorm (warp-per-row)
    rmsnorm_kernel<<<MM / 8, 256>>>(x, rms_scale, xn);

    // 2. Fused QKV projection (persistent)
    mma_gemm_kernel<1, true><<<GEMM_GRID, 256, GEMM_SMEM_BYTES>>>(
        xn, wqkvt, bqkv, pds, qkv, MM, QKVN, DD);

    // 3. Flash attention v5
    flash_kernel<<<dim3(TT / 128, BB * NHEAD), 256, FLASH_SMEM_BYTES>>>(
        qkv, padding, ao);

    // 4. Output projection + bias + residual(x) (persistent)
    mma_gemm_kernel<2, false><<<GEMM_GRID, 256, GEMM_SMEM_BYTES>>>(
        ao, wot, bo, x, ar, MM, DD, DD);

    // 5. LayerNorm (warp-per-row)
    layernorm_kernel<<<MM / 8, 256>>>(ar, ln_gamma, ln_beta, hn);

    // 6. FFN up + ReLU (persistent)
    mma_gemm_kernel<3, true><<<GEMM_GRID, 256, GEMM_SMEM_BYTES>>>(
        hn, w1t, b1, nullptr, h1, MM, FF, DD);

    // 7. FFN down + bias + residual(ar) -> output (persistent)
    mma_gemm_kernel<2, false><<<GEMM_GRID, 256, GEMM_SMEM_BYTES>>>(
        h1, w2t, b2, ar, out, MM, DD, FF);
}

// round 14
// speedup vs baseline: 1.0860x; 1.0860x over previous
#include <cuda_runtime.h>
#include <cuda_fp16.h>
#include <cstdint>
#include <math.h>

// Problem constants
#define BB 8
#define TT 1024
#define DD 1024
#define NHEAD 16
#define HDIM 64
#define FF 4096
#define MM (BB * TT)   // 8192
#define QKVN 3072

// ---------------------------------------------------------------------------
// Scratch (device globals)
// ---------------------------------------------------------------------------
__device__ __half g_xn [MM * DD];
__device__ __half g_qkv[MM * QKVN];
__device__ __half g_ao [MM * DD];
__device__ float  g_ar [MM * DD];
__device__ __half g_hn [MM * DD];
__device__ __half g_h1 [MM * FF];
__device__ __half g_wqkvt[QKVN * DD];   // [3072][1024] K-major (q|k|v)
__device__ float  g_bqkv [QKVN];
__device__ __half g_wot[DD * DD];
__device__ __half g_w1t[FF * DD];
__device__ __half g_w2t[DD * FF];

// ---------------------------------------------------------------------------
// Helpers
// ---------------------------------------------------------------------------
__device__ __forceinline__ uint32_t s2u(const void* p) {
    uint32_t a;
    asm("{ .reg .u64 t; cvta.to.shared.u64 t, %1; cvt.u32.u64 %0, t; }"
        : "=r"(a) : "l"(p));
    return a;
}

__device__ __forceinline__ void cp_async16(uint32_t saddr, const void* gaddr) {
    asm volatile("cp.async.cg.shared.global [%0], [%1], 16;"
                 :: "r"(saddr), "l"(gaddr));
}
__device__ __forceinline__ void cp_async4(uint32_t saddr, const void* gaddr) {
    asm volatile("cp.async.ca.shared.global [%0], [%1], 4;"
                 :: "r"(saddr), "l"(gaddr));
}
__device__ __forceinline__ void cp_commit() {
    asm volatile("cp.async.commit_group;");
}
template <int N>
__device__ __forceinline__ void cp_wait() {
    asm volatile("cp.async.wait_group %0;" :: "n"(N));
}

__device__ __forceinline__ void ldsm4(uint32_t& r0, uint32_t& r1,
                                      uint32_t& r2, uint32_t& r3, uint32_t addr) {
    asm volatile("ldmatrix.sync.aligned.m8n8.x4.shared.b16 {%0,%1,%2,%3}, [%4];"
                 : "=r"(r0), "=r"(r1), "=r"(r2), "=r"(r3) : "r"(addr));
}
__device__ __forceinline__ void ldsm4t(uint32_t& r0, uint32_t& r1,
                                       uint32_t& r2, uint32_t& r3, uint32_t addr) {
    asm volatile("ldmatrix.sync.aligned.m8n8.x4.trans.shared.b16 {%0,%1,%2,%3}, [%4];"
                 : "=r"(r0), "=r"(r1), "=r"(r2), "=r"(r3) : "r"(addr));
}

// fp16 MMA m16n8k16, fp32 accumulate
__device__ __forceinline__ void mma_f16(float* c, const uint32_t* a,
                                        uint32_t b0, uint32_t b1) {
    asm volatile(
        "mma.sync.aligned.m16n8k16.row.col.f32.f16.f16.f32 "
        "{%0,%1,%2,%3}, {%4,%5,%6,%7}, {%8,%9}, {%0,%1,%2,%3};"
        : "+f"(c[0]), "+f"(c[1]), "+f"(c[2]), "+f"(c[3])
        : "r"(a[0]), "r"(a[1]), "r"(a[2]), "r"(a[3]), "r"(b0), "r"(b1));
}

__device__ __forceinline__ uint32_t pkh2(float a, float b) {
    const __half2 h = __floats2half2_rn(a, b);
    return *(const uint32_t*)&h;
}

// ---------------------------------------------------------------------------
// Fused prep kernel: weight transposes + wo convert + bias concat + RMSNorm
// (rmsnorm depends only on x; prep only on weights -> safe to co-launch)
// ---------------------------------------------------------------------------
__device__ __forceinline__ void transpose_tile(
    const float* __restrict__ in, __half* __restrict__ out,
    int bx, int by, int C, int R, float (*t)[33], int tid)
{
    const int txx = tid & 31, tyy = tid >> 5;
    #pragma unroll
    for (int j = 0; j < 32; j += 8)
        t[tyy + j][txx] = in[(size_t)(by + tyy + j) * C + bx + txx];
    __syncthreads();
    #pragma unroll
    for (int j = 0; j < 32; j += 8)
        out[(size_t)(bx + tyy + j) * R + by + txx] = __float2half_rn(t[txx][tyy + j]);
}

#define PREP_BLOCKS (12300 + MM / 8)

__global__ __launch_bounds__(256) void prep_kernel(
    const float* __restrict__ wq, const float* __restrict__ wk,
    const float* __restrict__ wv, const float* __restrict__ w1,
    const float* __restrict__ w2, const float* __restrict__ wo,
    const float* __restrict__ bq, const float* __restrict__ bk,
    const float* __restrict__ bv,
    __half* __restrict__ wqkvt, __half* __restrict__ w1t,
    __half* __restrict__ w2t, __half* __restrict__ wot,
    float* __restrict__ bqkv,
    const float* __restrict__ x, const float* __restrict__ rms_scale,
    __half* __restrict__ xn)
{
    __shared__ float t[32][33];
    const int id = blockIdx.x;
    const int tid = threadIdx.x;

    if (id < 3072) {
        const int w = id >> 10, tt = id & 1023;
        const float* in = (w == 0) ? wq : (w == 1) ? wk : wv;
        __half* outp = wqkvt + (size_t)w * 1024 * DD;
        transpose_tile(in, outp, (tt & 31) << 5, (tt >> 5) << 5, DD, DD, t, tid);
    } else if (id < 7168) {
        const int tt = id - 3072;
        transpose_tile(w1, w1t, (tt & 127) << 5, (tt >> 7) << 5, FF, DD, t, tid);
    } else if (id < 11264) {
        const int tt = id - 7168;
        transpose_tile(w2, w2t, (tt & 31) << 5, (tt >> 5) << 5, DD, FF, t, tid);
    } else if (id < 12288) {
        const int i = (id - 11264) * 1024 + tid * 4;
        const float4 v = *(const float4*)(wo + i);
        __half2* o2 = (__half2*)(wot + i);
        o2[0] = __floats2half2_rn(v.x, v.y);
        o2[1] = __floats2half2_rn(v.z, v.w);
    } else if (id < 12300) {
        const int i = (id - 12288) * 256 + tid;
        if (i < QKVN)
            bqkv[i] = (i < 1024) ? bq[i] : (i < 2048) ? bk[i - 1024] : bv[i - 2048];
    } else {
        // RMSNorm: warp-per-row, 8 rows per block
        const int lane = tid & 31;
        const int row = (id - 12300) * 8 + (tid >> 5);
        const float4* xp = (const float4*)(x + (size_t)row * DD);
        const float4* sp = (const float4*)rms_scale;
        float4 v[8];
        float ss = 0.f;
        #pragma unroll
        for (int u = 0; u < 8; u++) {
            v[u] = xp[lane + 32 * u];
            ss += v[u].x * v[u].x + v[u].y * v[u].y + v[u].z * v[u].z + v[u].w * v[u].w;
        }
        #pragma unroll
        for (int m = 16; m; m >>= 1) ss += __shfl_xor_sync(0xffffffffu, ss, m);
        const float r = rsqrtf(ss * (1.0f / DD) + 1e-6f);
        __half2* o2 = (__half2*)(xn + (size_t)row * DD);
        #pragma unroll
        for (int u = 0; u < 8; u++) {
            const float4 s4 = sp[lane + 32 * u];
            o2[(lane + 32 * u) * 2 + 0] = __floats2half2_rn(v[u].x * r * s4.x,
                                                            v[u].y * r * s4.y);
            o2[(lane + 32 * u) * 2 + 1] = __floats2half2_rn(v[u].z * r * s4.z,
                                                            v[u].w * r * s4.w);
        }
    }
}

// ---------------------------------------------------------------------------
// LayerNorm: warp-per-row
// ---------------------------------------------------------------------------
__global__ __launch_bounds__(256) void layernorm_kernel(
    const float* __restrict__ x, const float* __restrict__ gamma,
    const float* __restrict__ beta, __half* __restrict__ out)
{
    const int lane = threadIdx.x & 31;
    const int row = blockIdx.x * 8 + (threadIdx.x >> 5);
    const float4* xp = (const float4*)(x + (size_t)row * DD);
    float4 v[8];
    float s = 0.f, ss = 0.f;
    #pragma unroll
    for (int u = 0; u < 8; u++) {
        v[u] = xp[lane + 32 * u];
        s  += v[u].x + v[u].y + v[u].z + v[u].w;
        ss += v[u].x * v[u].x + v[u].y * v[u].y + v[u].z * v[u].z + v[u].w * v[u].w;
    }
    #pragma unroll
    for (int m = 16; m; m >>= 1) {
        s  += __shfl_xor_sync(0xffffffffu, s,  m);
        ss += __shfl_xor_sync(0xffffffffu, ss, m);
    }
    const float mean = s * (1.0f / DD);
    const float var  = ss * (1.0f / DD) - mean * mean;
    const float r = rsqrtf(var + 1e-5f);
    __half2* o2 = (__half2*)(out + (size_t)row * DD);
    const float4* gp = (const float4*)gamma;
    const float4* bp = (const float4*)beta;
    #pragma unroll
    for (int u = 0; u < 8; u++) {
        const float4 g4 = gp[lane + 32 * u];
        const float4 b4 = bp[lane + 32 * u];
        o2[(lane + 32 * u) * 2 + 0] = __floats2half2_rn(
            (v[u].x - mean) * r * g4.x + b4.x, (v[u].y - mean) * r * g4.y + b4.y);
        o2[(lane + 32 * u) * 2 + 1] = __floats2half2_rn(
            (v[u].z - mean) * r * g4.z + b4.z, (v[u].w - mean) * r * g4.w + b4.w);
    }
}

// ---------------------------------------------------------------------------
// fp16 mma.sync GEMM (per-tile grid — R9 proven version)
// ---------------------------------------------------------------------------
__device__ __forceinline__ float softplus_f(float x) {
    return (x > 15.f) ? x : log1pf(__expf(x));
}

#define GSTAGE 32768
#define GEMM_SMEM_BYTES (3 * GSTAGE)

template <int EPI, bool OUTH>
__global__ __launch_bounds__(256, 2) void mma_gemm_kernel(
    const __half* __restrict__ A, const __half* __restrict__ Bw,
    const float* __restrict__ bias, const float* __restrict__ extra,
    void* __restrict__ Cv, int M, int N, int K)
{
    extern __shared__ char gsm[];
    const uint32_t smbase = s2u(gsm);
    const int tid = threadIdx.x;
    const int lane = tid & 31;
    const int wid = tid >> 5;
    const int m0 = blockIdx.y << 7;
    const int n0 = blockIdx.x << 7;
    const int wm = (wid & 3) << 5;
    const int wn = (wid >> 2) << 6;

    uint32_t a_soff[4], b_soff[4];
    const __half* a_g[4]; const __half* b_g[4];
    #pragma unroll
    for (int u = 0; u < 4; u++) {
        const int qch = tid + u * 256;
        const int m = qch >> 3, kc = qch & 7;
        const uint32_t sw = (uint32_t)(kc ^ (m & 7));
        a_soff[u] = (uint32_t)(m * 128) + (sw << 4);
        b_soff[u] = a_soff[u] + 16384u;
        a_g[u] = A  + (size_t)(m0 + m) * K + kc * 8;
        b_g[u] = Bw + (size_t)(n0 + m) * K + kc * 8;
    }

    const int arow = wm + (lane & 15);
    const uint32_t acadd = (uint32_t)(lane >> 4);
    const uint32_t aswz = (uint32_t)(arow & 7);
    const uint32_t aoff = (uint32_t)(arow * 128);
    const int brow = wn + ((lane >> 4) << 3) + (lane & 7);
    const uint32_t bcc = (uint32_t)((lane >> 3) & 1);
    const uint32_t bswz = (uint32_t)(brow & 7);
    const uint32_t boff = (uint32_t)(brow * 128) + 16384u;

    float acc[2][8][4];
    #pragma unroll
    for (int i = 0; i < 2; i++)
        #pragma unroll
        for (int j = 0; j < 8; j++)
            #pragma unroll
            for (int t = 0; t < 4; t++) acc[i][j][t] = 0.f;

    const int nk = K >> 6;
    #pragma unroll
    for (int s = 0; s < 2; s++) {
        const uint32_t sb = smbase + (uint32_t)s * GSTAGE;
        #pragma unroll
        for (int u = 0; u < 4; u++) {
            cp_async16(sb + a_soff[u], a_g[u] + s * 64);
            cp_async16(sb + b_soff[u], b_g[u] + s * 64);
        }
        cp_commit();
    }

    int sidx = 0;
    for (int kc = 0; kc < nk; kc++) {
        if (kc == nk - 1) cp_wait<0>(); else cp_wait<1>();
        __syncthreads();
        if (kc + 2 < nk) {
            const int s2 = (sidx + 2 >= 3) ? sidx - 1 : sidx + 2;
            const uint32_t sb = smbase + (uint32_t)s2 * GSTAGE;
            #pragma unroll
            for (int u = 0; u < 4; u++) {
                cp_async16(sb + a_soff[u], a_g[u] + (kc + 2) * 64);
                cp_async16(sb + b_soff[u], b_g[u] + (kc + 2) * 64);
            }
            cp_commit();
        }
        const uint32_t sb = smbase + (uint32_t)sidx * GSTAGE;
        #pragma unroll
        for (int ks = 0; ks < 4; ks++) {
            const uint32_t kc0 = (uint32_t)(2 * ks);
            uint32_t af[2][4];
            #pragma unroll
            for (int i = 0; i < 2; i++) {
                const uint32_t addr = sb + aoff + (uint32_t)(i * 2048) +
                                      (((kc0 + acadd) ^ aswz) << 4);
                ldsm4(af[i][0], af[i][1], af[i][2], af[i][3], addr);
            }
            #pragma unroll
            for (int jp = 0; jp < 4; jp++) {
                uint32_t b0, b1, b2, b3;
                const uint32_t addr = sb + boff + (uint32_t)(jp * 2048) +
                                      (((kc0 + bcc) ^ bswz) << 4);
                ldsm4(b0, b1, b2, b3, addr);
                #pragma unroll
                for (int i = 0; i < 2; i++) {
                    mma_f16(acc[i][2 * jp + 0], af[i], b0, b1);
                    mma_f16(acc[i][2 * jp + 1], af[i], b2, b3);
                }
            }
        }
        sidx = (sidx == 2) ? 0 : sidx + 1;
    }

    const int g = lane >> 2, tg = lane & 3;
    #pragma unroll
    for (int i = 0; i < 2; i++) {
        #pragma unroll
        for (int j = 0; j < 8; j++) {
            const int col = n0 + wn + j * 8 + tg * 2;
            const float2 b2 = *(const float2*)(bias + col);
            float sx = 1.f, sy = 1.f;
            if (EPI == 1) {
                if (col < 1024) {
                    // LOG2E^2 / sqrt(64): extra LOG2E folds softmax into exp2
                    const float c = 0.26017101f;
                    sx = c * softplus_f(extra[col & 63]);
                    sy = c * softplus_f(extra[(col + 1) & 63]);
                }
            }
            #pragma unroll
            for (int h = 0; h < 2; h++) {
                const int row = m0 + wm + i * 16 + g + h * 8;
                float vx = acc[i][j][2 * h + 0] + b2.x;
                float vy = acc[i][j][2 * h + 1] + b2.y;
                if (EPI == 1) { vx *= sx; vy *= sy; }
                if (EPI == 2) {
                    const float2 r2 = *(const float2*)(extra + (size_t)row * N + col);
                    vx += r2.x; vy += r2.y;
                }
                if (EPI == 3) { vx = fmaxf(vx, 0.f); vy = fmaxf(vy, 0.f); }
                if (OUTH) {
                    *(__half2*)((__half*)Cv + (size_t)row * N + col) =
                        __floats2half2_rn(vx, vy);
                } else {
                    float2 o2; o2.x = vx; o2.y = vy;
                    *(float2*)((float*)Cv + (size_t)row * N + col) = o2;
                }
            }
        }
    }
}

// ---------------------------------------------------------------------------
// Flash attention v5 (R9 proven version)
// ---------------------------------------------------------------------------
#define FL_PQ_I 12288   // float idx: padq[128]
#define FL_PS_I 12416   // pads[2][64]
#define FLASH_SMEM_BYTES 50176

__global__ __launch_bounds__(256) void flash_kernel(
    const __half* __restrict__ qkv, const float* __restrict__ pad,
    __half* __restrict__ out)
{
    extern __shared__ float sf[];
    const uint32_t sbase = s2u(sf);
    const int tid = threadIdx.x;
    const int lane = tid & 31;
    const int wid = tid >> 5;
    const int wm = wid << 4;
    const int g = lane >> 2, tg = lane & 3;
    const int t0 = (7 - blockIdx.x) << 7;         // longest first
    const int b = blockIdx.y >> 4, n = blockIdx.y & 15;

    const int arow = wm + (lane & 15);
    const uint32_t acadd = (uint32_t)(lane >> 4);
    const uint32_t aswz = (uint32_t)(arow & 7);
    const uint32_t qbase = sbase + (uint32_t)(arow * 128);
    const int brw = ((lane >> 4) << 3) + (lane & 7);
    const uint32_t bcc = (uint32_t)((lane >> 3) & 1);
    const int vkr = ((lane >> 3) & 1) * 8 + (lane & 7);
    const int vcc = lane >> 4;

    // ---- load Q tile + padq
    {
        const int r = tid >> 1;
        const int c0 = (tid & 1) << 2;
        const __half* qp = qkv + (size_t)(b * TT + t0 + r) * QKVN + n * 64;
        #pragma unroll
        for (int u = 0; u < 4; u++) {
            const int c = c0 + u;
            cp_async16(sbase + (uint32_t)(r * 128 + ((c ^ (r & 7)) << 4)),
                       qp + c * 8);
        }
        if (tid < 128)
            cp_async4(sbase + (uint32_t)((FL_PQ_I + tid) * 4),
                      pad + b * TT + t0 + tid);
    }
    // ---- prefetch first K/V tile into buf 0
    {
        const int lr = tid >> 2;
        const int lc0 = (tid & 3) << 1;
        const __half* kp = qkv + (size_t)(b * TT + lr) * QKVN + 1024 + n * 64;
        const __half* vp = kp + 1024;
        #pragma unroll
        for (int u = 0; u < 2; u++) {
            const int c = lc0 + u;
            const uint32_t so = (uint32_t)(lr * 128 + ((c ^ (lr & 7)) << 4));
            cp_async16(sbase + 16384u + so, kp + c * 8);
            cp_async16(sbase + 24576u + so, vp + c * 8);
        }
        if (tid < 64)
            cp_async4(sbase + (uint32_t)((FL_PS_I + tid) * 4), pad + b * TT + tid);
    }
    cp_commit();

    float o[8][4];
    #pragma unroll
    for (int j = 0; j < 8; j++)
        #pragma unroll
        for (int c = 0; c < 4; c++) o[j][c] = 0.f;
    float m0 = -1e30f, m1 = -1e30f, l0 = 0.f, l1 = 0.f;
    const int r0l = wm + g, r1l = r0l + 8;

    const int nIter = (t0 >> 6) + 2;
    for (int it = 0; it < nIter; it++) {
        const int s0 = it << 6;
        const int buf = it & 1;
        const uint32_t kbuf = sbase + 16384u + (uint32_t)buf * 16384u;
        const uint32_t vbuf = kbuf + 8192u;

        cp_wait<0>();
        __syncthreads();

        if (it + 1 < nIter) {
            const int lr = tid >> 2;
            const int lc0 = (tid & 3) << 1;
            const __half* kp = qkv + (size_t)(b * TT + s0 + 64 + lr) * QKVN + 1024 + n * 64;
            const __half* vp = kp + 1024;
            const uint32_t ob = sbase + 16384u + (uint32_t)(buf ^ 1) * 16384u;
            #pragma unroll
            for (int u = 0; u < 2; u++) {
                const int c = lc0 + u;
                const uint32_t so = (uint32_t)(lr * 128 + ((c ^ (lr & 7)) << 4));
                cp_async16(ob + so, kp + c * 8);
                cp_async16(ob + 8192u + so, vp + c * 8);
            }
            if (tid < 64)
                cp_async4(sbase + (uint32_t)((FL_PS_I + (buf ^ 1) * 64 + tid) * 4),
                          pad + b * TT + s0 + 64 + tid);
            cp_commit();
        }

        // ---- S = Q K^T
        float sacc[8][4];
        #pragma unroll
        for (int j = 0; j < 8; j++)
            #pragma unroll
            for (int c = 0; c < 4; c++) sacc[j][c] = 0.f;
        #pragma unroll
        for (int ks = 0; ks < 4; ks++) {
            const uint32_t kc0 = (uint32_t)(2 * ks);
            uint32_t af[4];
            ldsm4(af[0], af[1], af[2], af[3],
                  qbase + (((kc0 + acadd) ^ aswz) << 4));
            #pragma unroll
            for (int jp = 0; jp < 4; jp++) {
                const int brow = jp * 16 + brw;
                uint32_t b0, b1, b2, b3;
                ldsm4(b0, b1, b2, b3,
                      kbuf + (uint32_t)(brow * 128) +
                      (((kc0 + bcc) ^ (uint32_t)(brow & 7)) << 4));
                mma_f16(sacc[2 * jp + 0], af, b0, b1);
                mma_f16(sacc[2 * jp + 1], af, b2, b3);
            }
        }

        // ---- additive masking (warp-uniform causal branch)
        const float pq0 = sf[FL_PQ_I + r0l], pq1 = sf[FL_PQ_I + r1l];
        const float pqa0 = (pq0 != 0.f) ? 0.f : -1e9f;
        const float pqa1 = (pq1 != 0.f) ? 0.f : -1e9f;
        const int rg0 = t0 + r0l, rg1 = t0 + r1l;
        const int psb = FL_PS_I + buf * 64;
        if (s0 + 64 <= t0 + wm) {
            #pragma unroll
            for (int j = 0; j < 8; j++) {
                const int cl = j * 8 + 2 * tg;
                const float psa0 = (sf[psb + cl]     != 0.f) ? 0.f : -1e9f;
                const float psa1 = (sf[psb + cl + 1] != 0.f) ? 0.f : -1e9f;
                sacc[j][0] += pqa0 + psa0;
                sacc[j][1] += pqa0 + psa1;
                sacc[j][2] += pqa1 + psa0;
                sacc[j][3] += pqa1 + psa1;
            }
        } else {
            #pragma unroll
            for (int j = 0; j < 8; j++) {
                const int cl = j * 8 + 2 * tg;
                const int cg = s0 + cl;
                const float psa0 = (sf[psb + cl]     != 0.f) ? 0.f : -1e9f;
                const float psa1 = (sf[psb + cl + 1] != 0.f) ? 0.f : -1e9f;
                sacc[j][0] += pqa0 + psa0 + ((cg     <= rg0) ? 0.f : -1e9f);
                sacc[j][1] += pqa0 + psa1 + ((cg + 1 <= rg0) ? 0.f : -1e9f);
                sacc[j][2] += pqa1 + psa0 + ((cg     <= rg1) ? 0.f : -1e9f);
                sacc[j][3] += pqa1 + psa1 + ((cg + 1 <= rg1) ? 0.f : -1e9f);
            }
        }

        // ---- warp-local online softmax in log2 domain
        float rm0 = -1e30f, rm1 = -1e30f;
        #pragma unroll
        for (int j = 0; j < 8; j++) {
            rm0 = fmaxf(rm0, fmaxf(sacc[j][0], sacc[j][1]));
            rm1 = fmaxf(rm1, fmaxf(sacc[j][2], sacc[j][3]));
        }
        rm0 = fmaxf(rm0, __shfl_xor_sync(0xffffffffu, rm0, 1));
        rm0 = fmaxf(rm0, __shfl_xor_sync(0xffffffffu, rm0, 2));
        rm1 = fmaxf(rm1, __shfl_xor_sync(0xffffffffu, rm1, 1));
        rm1 = fmaxf(rm1, __shfl_xor_sync(0xffffffffu, rm1, 2));
        const float mn0 = fmaxf(m0, rm0), mn1 = fmaxf(m1, rm1);
        const float alpha0 = exp2f(m0 - mn0), alpha1 = exp2f(m1 - mn1);
        m0 = mn0; m1 = mn1;
        float rs0 = 0.f, rs1 = 0.f;
        #pragma unroll
        for (int j = 0; j < 8; j++) {
            sacc[j][0] = exp2f(sacc[j][0] - mn0);
            sacc[j][1] = exp2f(sacc[j][1] - mn0);
            sacc[j][2] = exp2f(sacc[j][2] - mn1);
            sacc[j][3] = exp2f(sacc[j][3] - mn1);
            rs0 += sacc[j][0] + sacc[j][1];
            rs1 += sacc[j][2] + sacc[j][3];
        }
        rs0 += __shfl_xor_sync(0xffffffffu, rs0, 1);
        rs0 += __shfl_xor_sync(0xffffffffu, rs0, 2);
        rs1 += __shfl_xor_sync(0xffffffffu, rs1, 1);
        rs1 += __shfl_xor_sync(0xffffffffu, rs1, 2);
        l0 = l0 * alpha0 + rs0;
        l1 = l1 * alpha1 + rs1;
        #pragma unroll
        for (int j = 0; j < 8; j++) {
            o[j][0] *= alpha0; o[j][1] *= alpha0;
            o[j][2] *= alpha1; o[j][3] *= alpha1;
        }

        // ---- pack P into 4 k16 A-fragments
        uint32_t pa[4][4];
        #pragma unroll
        for (int ks = 0; ks < 4; ks++) {
            pa[ks][0] = pkh2(sacc[2 * ks][0],     sacc[2 * ks][1]);
            pa[ks][1] = pkh2(sacc[2 * ks][2],     sacc[2 * ks][3]);
            pa[ks][2] = pkh2(sacc[2 * ks + 1][0], sacc[2 * ks + 1][1]);
            pa[ks][3] = pkh2(sacc[2 * ks + 1][2], sacc[2 * ks + 1][3]);
        }

        // ---- O += P V
        #pragma unroll
        for (int ks = 0; ks < 4; ks++) {
            const int kr = ks * 16 + vkr;
            #pragma unroll
            for (int jp = 0; jp < 4; jp++) {
                const int c = jp * 2 + vcc;
                uint32_t b0, b1, b2, b3;
                ldsm4t(b0, b1, b2, b3,
                       vbuf + (uint32_t)(kr * 128) +
                       (((uint32_t)c ^ (uint32_t)(kr & 7)) << 4));
                mma_f16(o[2 * jp + 0], pa[ks], b0, b1);
                mma_f16(o[2 * jp + 1], pa[ks], b2, b3);
            }
        }
    }

    // ---- finalize
    const float inv0 = 1.f / l0;
    const float inv1 = 1.f / l1;
    const size_t row0 = (size_t)(b * TT + t0 + r0l);
    const size_t row1 = (size_t)(b * TT + t0 + r1l);
    #pragma unroll
    for (int j = 0; j < 8; j++) {
        const int col = n * 64 + j * 8 + 2 * tg;
        *(__half2*)(out + row0 * DD + col) =
            __floats2half2_rn(o[j][0] * inv0, o[j][1] * inv0);
        *(__half2*)(out + row1 * DD + col) =
            __floats2half2_rn(o[j][2] * inv1, o[j][3] * inv1);
    }
}

// ---------------------------------------------------------------------------
// Host launch
// ---------------------------------------------------------------------------
extern "C" void kernel_launch(void* const* d_in, const int* in_sizes, int n_in,
                              void* d_out, int out_size)
{
    (void)in_sizes; (void)n_in; (void)out_size;
    const float* x         = (const float*)d_in[0];
    const float* padding   = (const float*)d_in[1];
    const float* rms_scale = (const float*)d_in[2];
    const float* pds       = (const float*)d_in[3];
    const float* wq        = (const float*)d_in[4];
    const float* bq        = (const float*)d_in[5];
    const float* wk        = (const float*)d_in[6];
    const float* bk        = (const float*)d_in[7];
    const float* wv        = (const float*)d_in[8];
    const float* bv        = (const float*)d_in[9];
    const float* wo        = (const float*)d_in[10];
    const float* bo        = (const float*)d_in[11];
    const float* ln_gamma  = (const float*)d_in[12];
    const float* ln_beta   = (const float*)d_in[13];
    const float* w1        = (const float*)d_in[14];
    const float* b1        = (const float*)d_in[15];
    const float* w2        = (const float*)d_in[16];
    const float* b2        = (const float*)d_in[17];
    float* out = (float*)d_out;

    __half *xn, *qkv, *ao, *hn, *h1, *wqkvt, *wot, *w1t, *w2t;
    float *ar, *bqkv;
    cudaGetSymbolAddress((void**)&xn,  g_xn);
    cudaGetSymbolAddress((void**)&qkv, g_qkv);
    cudaGetSymbolAddress((void**)&ao,  g_ao);
    cudaGetSymbolAddress((void**)&ar,  g_ar);
    cudaGetSymbolAddress((void**)&hn,  g_hn);
    cudaGetSymbolAddress((void**)&h1,  g_h1);
    cudaGetSymbolAddress((void**)&wqkvt, g_wqkvt);
    cudaGetSymbolAddress((void**)&bqkv,  g_bqkv);
    cudaGetSymbolAddress((void**)&wot, g_wot);
    cudaGetSymbolAddress((void**)&w1t, g_w1t);
    cudaGetSymbolAddress((void**)&w2t, g_w2t);

    static int attr_done = 0;
    if (!attr_done) {
        cudaFuncSetAttribute(flash_kernel,
            cudaFuncAttributeMaxDynamicSharedMemorySize, FLASH_SMEM_BYTES);
        cudaFuncSetAttribute(mma_gemm_kernel<1, true>,
            cudaFuncAttributeMaxDynamicSharedMemorySize, GEMM_SMEM_BYTES);
        cudaFuncSetAttribute(mma_gemm_kernel<2, false>,
            cudaFuncAttributeMaxDynamicSharedMemorySize, GEMM_SMEM_BYTES);
        cudaFuncSetAttribute(mma_gemm_kernel<3, true>,
            cudaFuncAttributeMaxDynamicSharedMemorySize, GEMM_SMEM_BYTES);
        attr_done = 1;
    }

    // 0. Fused weight prep + RMSNorm (independent work, one launch)
    prep_kernel<<<PREP_BLOCKS, 256>>>(wq, wk, wv, w1, w2, wo, bq, bk, bv,
                                      wqkvt, w1t, w2t, wot, bqkv,
                                      x, rms_scale, xn);

    // 1. Fused QKV projection (per-tile grid; q pre-scaled for exp2 softmax)
    dim3 gQKV(QKVN / 128, MM / 128);
    mma_gemm_kernel<1, true><<<gQKV, 256, GEMM_SMEM_BYTES>>>(
        xn, wqkvt, bqkv, pds, qkv, MM, QKVN, DD);

    // 2. Flash attention v5
    flash_kernel<<<dim3(TT / 128, BB * NHEAD), 256, FLASH_SMEM_BYTES>>>(
        qkv, padding, ao);

    // 3. Output projection + bias + residual(x)
    dim3 gD(DD / 128, MM / 128);
    mma_gemm_kernel<2, false><<<gD, 256, GEMM_SMEM_BYTES>>>(
        ao, wot, bo, x, ar, MM, DD, DD);

    // 4. LayerNorm (warp-per-row)
    layernorm_kernel<<<MM / 8, 256>>>(ar, ln_gamma, ln_beta, hn);

    // 5. FFN up + ReLU
    dim3 gF(FF / 128, MM / 128);
    mma_gemm_kernel<3, true><<<gF, 256, GEMM_SMEM_BYTES>>>(
        hn, w1t, b1, nullptr, h1, MM, FF, DD);

    // 6. FFN down + bias + residual(ar) -> output
    mma_gemm_kernel<2, false><<<gD, 256, GEMM_SMEM_BYTES>>>(
        h1, w2t, b2, ar, out, MM, DD, FF);
}